// round 2
// baseline (speedup 1.0000x reference)
#include <cuda_runtime.h>

// ---------------------------------------------------------------------------
// QuantumDecoder: z -> tanh(z@W_in) -> 4-qubit circuit Z-expectations ->
//                 relu(@W1) -> sigmoid(@W2)
//
// The post-RY circuit (RX/RY/RZ with fixed theta + CX ring, 2 layers) is a
// fixed 16x16 unitary M. With real product state s0 from the RY layer:
//   z_q = s0^T * Re(M^H Z_q M) * s0      (real symmetric quadratic form)
// A setup kernel simulates the 16 basis columns and builds the 4 matrices.
// ---------------------------------------------------------------------------

__device__ float g_A[4 * 16 * 16];   // Re(M^H Z_q M), q = 0..3

// ---- packed f32x2 helpers (Blackwell) -------------------------------------
__device__ __forceinline__ unsigned long long pack2(float x, float y) {
    unsigned long long r;
    asm("mov.b64 %0, {%1, %2};" : "=l"(r) : "f"(x), "f"(y));
    return r;
}
__device__ __forceinline__ void unpack2(unsigned long long v, float& x, float& y) {
    asm("mov.b64 {%0, %1}, %2;" : "=f"(x), "=f"(y) : "l"(v));
}
__device__ __forceinline__ unsigned long long ffma2(unsigned long long a,
                                                    unsigned long long b,
                                                    unsigned long long c) {
    unsigned long long d;
    asm("fma.rn.f32x2 %0, %1, %2, %3;" : "=l"(d) : "l"(a), "l"(b), "l"(c));
    return d;
}
__device__ __forceinline__ float sigmoidf_fast(float x) {
    float e = __expf(-x);                 // MUFU.EX2 path
    return __fdividef(1.0f, 1.0f + e);    // MUFU.RCP path
}

// ---------------------------------------------------------------------------
// Setup kernel: simulate the fixed part of the circuit on the 16 basis
// states, then build A_q = Re(M^H Z_q M).  Runs once per launch, trivial cost.
// ---------------------------------------------------------------------------
__global__ void qd_setup_kernel(const float* __restrict__ theta) {
    __shared__ float2 M[16][16];   // M[x][j] = <x| circuit |j>
    int tid = threadIdx.x;

    if (tid < 16) {
        float2 st[16];
        for (int x = 0; x < 16; x++) st[x] = make_float2(0.f, 0.f);
        st[tid] = make_float2(1.f, 0.f);

        for (int layer = 0; layer < 2; layer++) {
            for (int q = 0; q < 4; q++) {
                float th = theta[layer * 4 + q];
                float ch = cosf(0.5f * th), sh = sinf(0.5f * th);
                int bit = 1 << q;
                for (int a = 0; a < 8; a++) {
                    int i0 = ((a >> q) << (q + 1)) | (a & (bit - 1));
                    int i1 = i0 | bit;
                    float2 x0 = st[i0], x1 = st[i1];
                    // Rx = [[c, -i s], [-i s, c]]
                    float2 y0 = make_float2(ch * x0.x + sh * x1.y, ch * x0.y - sh * x1.x);
                    float2 y1 = make_float2(ch * x1.x + sh * x0.y, ch * x1.y - sh * x0.x);
                    // Ry = [[c, -s], [s, c]]
                    float2 z0 = make_float2(ch * y0.x - sh * y1.x, ch * y0.y - sh * y1.y);
                    float2 z1 = make_float2(sh * y0.x + ch * y1.x, sh * y0.y + ch * y1.y);
                    // Rz = diag(c - i s, c + i s)
                    st[i0] = make_float2(ch * z0.x + sh * z0.y, ch * z0.y - sh * z0.x);
                    st[i1] = make_float2(ch * z1.x - sh * z1.y, ch * z1.y + sh * z1.x);
                }
            }
            // CX ring: (c,t) = (0,1),(1,2),(2,3),(3,0); new[m] = old[m ^ (bit_c(m)<<t)]
            const int cs[4] = {0, 1, 2, 3};
            const int ts[4] = {1, 2, 3, 0};
            for (int g = 0; g < 4; g++) {
                float2 tmp[16];
                int c = cs[g], t = ts[g];
                for (int m = 0; m < 16; m++) tmp[m] = st[m ^ (((m >> c) & 1) << t)];
                for (int m = 0; m < 16; m++) st[m] = tmp[m];
            }
        }
        for (int x = 0; x < 16; x++) M[x][tid] = st[x];
    }
    __syncthreads();

    for (int idx = tid; idx < 1024; idx += blockDim.x) {
        int q = idx >> 8, i = (idx >> 4) & 15, j = idx & 15;
        float s = 0.f;
        for (int x = 0; x < 16; x++) {
            float2 mi = M[x][i], mj = M[x][j];
            float d = mi.x * mj.x + mi.y * mj.y;   // Re(conj(M[x,i]) * M[x,j])
            s += ((x >> q) & 1) ? -d : d;
        }
        g_A[idx] = s;
    }
}

// ---------------------------------------------------------------------------
// Main kernel: one thread = one batch row.
// ---------------------------------------------------------------------------
__global__ void __launch_bounds__(128, 4) qd_main_kernel(
    const float* __restrict__ z,   const float* __restrict__ W_in,
    const float* __restrict__ b_in, const float* __restrict__ W1,
    const float* __restrict__ b1,  const float* __restrict__ W2,
    const float* __restrict__ b2,  float* __restrict__ out)
{
    __shared__ float4 sWin[128];        // W_in [128][4], one float4 per k-row
    __shared__ float  sA[1024];         // A_q matrices
    __shared__ float  sW1[32];          // W1 [4][8]
    __shared__ float  sb1[8];
    __shared__ float  sbin[4];
    __shared__ float4 sW2[8 * 196];     // W2 [8][784] as float4
    __shared__ float4 sb2[196];

    int tid = threadIdx.x;
    sWin[tid] = ((const float4*)W_in)[tid];
    for (int i = tid; i < 1024; i += 128) sA[i] = g_A[i];
    if (tid < 32) sW1[tid] = W1[tid];
    if (tid < 8)  sb1[tid] = b1[tid];
    if (tid < 4)  sbin[tid] = b_in[tid];
    for (int i = tid; i < 8 * 196; i += 128) sW2[i] = ((const float4*)W2)[i];
    for (int i = tid; i < 196; i += 128) sb2[i] = ((const float4*)b2)[i];
    __syncthreads();

    int r = blockIdx.x * 128 + tid;

    // ---- 1) lat = tanh(z_row @ W_in + b_in) -------------------------------
    const float4* zp = (const float4*)(z + (size_t)r * 128);
    float ax = sbin[0], ay = sbin[1], az = sbin[2], aw = sbin[3];
#pragma unroll 8
    for (int k = 0; k < 32; k++) {
        float4 zv = zp[k];
        float4 wa = sWin[4 * k + 0], wb = sWin[4 * k + 1];
        float4 wc = sWin[4 * k + 2], wd = sWin[4 * k + 3];
        ax = fmaf(zv.x, wa.x, ax); ay = fmaf(zv.x, wa.y, ay);
        az = fmaf(zv.x, wa.z, az); aw = fmaf(zv.x, wa.w, aw);
        ax = fmaf(zv.y, wb.x, ax); ay = fmaf(zv.y, wb.y, ay);
        az = fmaf(zv.y, wb.z, az); aw = fmaf(zv.y, wb.w, aw);
        ax = fmaf(zv.z, wc.x, ax); ay = fmaf(zv.z, wc.y, ay);
        az = fmaf(zv.z, wc.z, az); aw = fmaf(zv.z, wc.w, aw);
        ax = fmaf(zv.w, wd.x, ax); ay = fmaf(zv.w, wd.y, ay);
        az = fmaf(zv.w, wd.z, az); aw = fmaf(zv.w, wd.w, aw);
    }
    float a0 = tanhf(ax), a1 = tanhf(ay), a2 = tanhf(az), a3 = tanhf(aw);

    // ---- 2) s0: real RY product state -------------------------------------
    float c0, s0s, c1, s1s, c2, s2s, c3, s3s;
    sincosf(0.5f * a0, &s0s, &c0);
    sincosf(0.5f * a1, &s1s, &c1);
    sincosf(0.5f * a2, &s2s, &c2);
    sincosf(0.5f * a3, &s3s, &c3);
    float u0 = c0 * c1, u1 = s0s * c1, u2 = c0 * s1s, u3 = s0s * s1s;
    float v0 = c2 * c3, v1 = s2s * c3, v2 = c2 * s3s, v3 = s2s * s3s;
    float st[16];
    st[0]  = u0 * v0; st[1]  = u1 * v0; st[2]  = u2 * v0; st[3]  = u3 * v0;
    st[4]  = u0 * v1; st[5]  = u1 * v1; st[6]  = u2 * v1; st[7]  = u3 * v1;
    st[8]  = u0 * v2; st[9]  = u1 * v2; st[10] = u2 * v2; st[11] = u3 * v2;
    st[12] = u0 * v3; st[13] = u1 * v3; st[14] = u2 * v3; st[15] = u3 * v3;

    // ---- 3) z_q = s0^T A_q s0 (packed f32x2) ------------------------------
    unsigned long long sp[8];   // adjacent-pair packed s0
    unsigned long long bi[16];  // broadcast-pair packed s0
#pragma unroll
    for (int j = 0; j < 8; j++) sp[j] = pack2(st[2 * j], st[2 * j + 1]);
#pragma unroll
    for (int i = 0; i < 16; i++) bi[i] = pack2(st[i], st[i]);

    const unsigned long long* A2 = (const unsigned long long*)sA;  // pairs along j
    float zq[4];
#pragma unroll
    for (int q = 0; q < 4; q++) {
        unsigned long long acc2 = 0ull;
#pragma unroll
        for (int jp = 0; jp < 8; jp++) {
            unsigned long long w2 = 0ull;   // (A s0) pair
#pragma unroll
            for (int i = 0; i < 16; i++)
                w2 = ffma2(A2[q * 128 + i * 8 + jp], bi[i], w2);
            acc2 = ffma2(sp[jp], w2, acc2);
        }
        float lo, hi;
        unpack2(acc2, lo, hi);
        zq[q] = lo + hi;
    }

    // ---- 4) h = relu(qexp @ W1 + b1);  qexp[k] = zq[3-k] ------------------
    float h[8];
#pragma unroll
    for (int m = 0; m < 8; m++) {
        float t = sb1[m];
        t = fmaf(zq[3], sW1[0 * 8 + m], t);
        t = fmaf(zq[2], sW1[1 * 8 + m], t);
        t = fmaf(zq[1], sW1[2 * 8 + m], t);
        t = fmaf(zq[0], sW1[3 * 8 + m], t);
        h[m] = fmaxf(t, 0.f);
    }

    // ---- 5) out = sigmoid(h @ W2 + b2), packed f32x2 ----------------------
    unsigned long long h2[8];
#pragma unroll
    for (int k = 0; k < 8; k++) h2[k] = pack2(h[k], h[k]);

    float4* op = (float4*)(out + (size_t)r * 784);
    const ulonglong2* W2p = (const ulonglong2*)sW2;
    const ulonglong2* b2p = (const ulonglong2*)sb2;
#pragma unroll 2
    for (int og = 0; og < 196; og++) {
        ulonglong2 bb = b2p[og];
        unsigned long long acc0 = bb.x, acc1 = bb.y;
#pragma unroll
        for (int k = 0; k < 8; k++) {
            ulonglong2 w = W2p[k * 196 + og];
            acc0 = ffma2(h2[k], w.x, acc0);
            acc1 = ffma2(h2[k], w.y, acc1);
        }
        float f0, f1, f2, f3;
        unpack2(acc0, f0, f1);
        unpack2(acc1, f2, f3);
        op[og] = make_float4(sigmoidf_fast(f0), sigmoidf_fast(f1),
                             sigmoidf_fast(f2), sigmoidf_fast(f3));
    }
}

// ---------------------------------------------------------------------------
extern "C" void kernel_launch(void* const* d_in, const int* in_sizes, int n_in,
                              void* d_out, int out_size) {
    const float* z     = (const float*)d_in[0];
    const float* W_in  = (const float*)d_in[1];
    const float* b_in  = (const float*)d_in[2];
    const float* theta = (const float*)d_in[3];
    const float* W1    = (const float*)d_in[4];
    const float* b1    = (const float*)d_in[5];
    const float* W2    = (const float*)d_in[6];
    const float* b2    = (const float*)d_in[7];

    int B = in_sizes[0] / 128;          // 65536
    qd_setup_kernel<<<1, 128>>>(theta);
    qd_main_kernel<<<B / 128, 128>>>(z, W_in, b_in, W1, b1, W2, b2, (float*)d_out);
}